// round 10
// baseline (speedup 1.0000x reference)
#include <cuda_runtime.h>
#include <cuda_bf16.h>
#include <math.h>
#include <stdint.h>

// Problem dimensions (fixed)
#define Bq   2
#define Lq   1024
#define Hq   768
#define DIq  1536
#define Nq   16
#define Kq   4
#define Rq   48
#define TB   (Bq*Lq)          // 2048 tokens
#define H1   (2*DIq*4)        // 12288
#define H2   (2*DIq)          // 3072
#define H3   (4*DIq)          // 6144
#define SSMW (Rq + 2*Nq)      // 80

// -------- fp32 scratch --------
__device__ __align__(16) float g_proj  [(size_t)TB * H2];
__device__ __align__(16) float g_hsconv[(size_t)TB * DIq];
__device__ __align__(16) float g_ssmp  [(size_t)TB * SSMW];
__device__ __align__(16) float g_dt    [(size_t)TB * DIq];

// -------- bf16 split scratch: hi in [0, n), lo in [n, 2n) --------
__device__ __align__(16) __nv_bfloat16 g_x_bf [2*(size_t)TB*Hq];
__device__ __align__(16) __nv_bfloat16 g_h1_bf[2*(size_t)TB*H1];
__device__ __align__(16) __nv_bfloat16 g_y_bf [2*(size_t)TB*DIq];
__device__ __align__(16) __nv_bfloat16 g_o1_bf[2*(size_t)TB*H3];
__device__ __align__(16) __nv_bfloat16 g_w1_bf[2*(size_t)H1*Hq];
__device__ __align__(16) __nv_bfloat16 g_w2_bf[2*(size_t)H2*H1];
__device__ __align__(16) __nv_bfloat16 g_w3_bf[2*(size_t)H3*DIq];
__device__ __align__(16) __nv_bfloat16 g_w4_bf[2*(size_t)Hq*H3];

__device__ __forceinline__ float silu_f(float x) {
    return x * (1.0f / (1.0f + __expf(-x)));
}

// ============================================================================
// fp32 -> (bf16 hi, bf16 lo) splitter.
// ============================================================================
__global__ void split_kernel(const float4* __restrict__ src,
                             uint2* __restrict__ dhi, size_t n4)
{
    size_t i = (size_t)blockIdx.x * blockDim.x + threadIdx.x;
    size_t stride = (size_t)gridDim.x * blockDim.x;
    uint2* dlo = dhi + n4;
    for (; i < n4; i += stride) {
        float4 v = src[i];
        __nv_bfloat162 h01 = __floats2bfloat162_rn(v.x, v.y);
        __nv_bfloat162 h23 = __floats2bfloat162_rn(v.z, v.w);
        float lx = v.x - __bfloat162float(h01.x);
        float ly = v.y - __bfloat162float(h01.y);
        float lz = v.z - __bfloat162float(h23.x);
        float lw = v.w - __bfloat162float(h23.y);
        __nv_bfloat162 l01 = __floats2bfloat162_rn(lx, ly);
        __nv_bfloat162 l23 = __floats2bfloat162_rn(lz, lw);
        dhi[i] = make_uint2(*(const uint32_t*)&h01, *(const uint32_t*)&h23);
        dlo[i] = make_uint2(*(const uint32_t*)&l01, *(const uint32_t*)&l23);
    }
}

// ============================================================================
// Common PTX helpers
// ============================================================================
__device__ __forceinline__ uint32_t smem_u32(const void* p) {
    uint32_t a;
    asm("{ .reg .u64 t; cvta.to.shared.u64 t, %1; cvt.u32.u64 %0, t; }"
        : "=r"(a) : "l"(p));
    return a;
}
__device__ __forceinline__ void cp16(uint32_t saddr, const void* g) {
    asm volatile("cp.async.cg.shared.global [%0], [%1], 16;" :: "r"(saddr), "l"(g));
}
__device__ __forceinline__ void ldsm4(uint32_t addr, uint32_t* r) {
    asm volatile("ldmatrix.sync.aligned.m8n8.x4.shared.b16 {%0,%1,%2,%3}, [%4];"
        : "=r"(r[0]), "=r"(r[1]), "=r"(r[2]), "=r"(r[3]) : "r"(addr));
}
__device__ __forceinline__ void mma16816(float* d, const uint32_t* a, const uint32_t* b) {
    asm volatile("mma.sync.aligned.m16n8k16.row.col.f32.bf16.bf16.f32 "
        "{%0,%1,%2,%3}, {%4,%5,%6,%7}, {%8,%9}, {%0,%1,%2,%3};"
        : "+f"(d[0]), "+f"(d[1]), "+f"(d[2]), "+f"(d[3])
        : "r"(a[0]), "r"(a[1]), "r"(a[2]), "r"(a[3]), "r"(b[0]), "r"(b[1]));
}

__device__ __forceinline__ void epilogue_store(
    int ACT, int OUTMODE, void* Cout, size_t c_lo, int N,
    int row, int col, float f0, float f1, float f2, float f3)
{
    if (ACT == 1) { f0 = silu_f(f0); f1 = silu_f(f1); f2 = silu_f(f2); f3 = silu_f(f3); }
    if (OUTMODE == 0) {
        float* C = (float*)Cout;
        *(float2*)(C + (size_t)row * N + col)       = make_float2(f0, f1);
        *(float2*)(C + (size_t)(row + 8) * N + col) = make_float2(f2, f3);
    } else {
        __nv_bfloat16* Ch = (__nv_bfloat16*)Cout;
        __nv_bfloat162 h01 = __floats2bfloat162_rn(f0, f1);
        __nv_bfloat162 l01 = __floats2bfloat162_rn(f0 - __bfloat162float(h01.x),
                                                   f1 - __bfloat162float(h01.y));
        __nv_bfloat162 h23 = __floats2bfloat162_rn(f2, f3);
        __nv_bfloat162 l23 = __floats2bfloat162_rn(f2 - __bfloat162float(h23.x),
                                                   f3 - __bfloat162float(h23.y));
        *(__nv_bfloat162*)(Ch + (size_t)row * N + col)              = h01;
        *(__nv_bfloat162*)(Ch + c_lo + (size_t)row * N + col)       = l01;
        *(__nv_bfloat162*)(Ch + (size_t)(row + 8) * N + col)        = h23;
        *(__nv_bfloat162*)(Ch + c_lo + (size_t)(row + 8) * N + col) = l23;
    }
}

// ============================================================================
// 3xBF16 NT GEMM, BM=256 BN=128 BK=32, 512 threads (16 warps, 4x4),
// 2 stages, 1 CTA/SM.  Traffic per output: 1.5x less than 128x128.
// ============================================================================
#define ROW_B     80
#define A256_B    (256*ROW_B)           // 20480 per A limb tile
#define B256_B    (128*ROW_B)           // 10240 per B limb tile
#define STAGE256  (2*A256_B + 2*B256_B) // 61440
#define TCSMEM256 (2*STAGE256)          // 122880

template<int ACT, int OUTMODE>
__global__ __launch_bounds__(512, 1) void tc_gemm256(
    const __nv_bfloat16* __restrict__ A, size_t a_lo,
    const __nv_bfloat16* __restrict__ B, size_t b_lo,
    void* __restrict__ Cout, size_t c_lo,
    int N, int K)
{
    extern __shared__ char smem[];
    const uint32_t sbase = smem_u32(smem);
    const int tid  = threadIdx.x;
    const int wid  = tid >> 5;
    const int lane = tid & 31;
    const int m0 = blockIdx.y * 256;
    const int n0 = blockIdx.x * 128;
    const int wy = wid & 3;         // m quarter (0..3) of 64 rows
    const int wx = wid >> 2;        // n quarter (0..3) of 32 cols

    // cp.async mapping
    const int rowA = tid >> 1;            // 0..255
    const int kcpA = (tid & 1) * 2;       // kc pair {0,1} or {2,3}
    const int rowB = tid >> 2;            // 0..127
    const int kcB  = tid & 3;

    auto issue = [&](int s, int kt) {
        const uint32_t st = sbase + (uint32_t)s * STAGE256;
        const size_t ka = (size_t)kt * 32;
        const __nv_bfloat16* pa = A + (size_t)(m0 + rowA) * K + ka;
        cp16(st +          rowA*ROW_B + kcpA*16,      pa + kcpA*8);
        cp16(st +          rowA*ROW_B + kcpA*16 + 16, pa + kcpA*8 + 8);
        cp16(st + A256_B + rowA*ROW_B + kcpA*16,      pa + a_lo + kcpA*8);
        cp16(st + A256_B + rowA*ROW_B + kcpA*16 + 16, pa + a_lo + kcpA*8 + 8);
        const __nv_bfloat16* pb = B + (size_t)(n0 + rowB) * K + ka + kcB*8;
        cp16(st + 2*A256_B +          rowB*ROW_B + kcB*16, pb);
        cp16(st + 2*A256_B + B256_B + rowB*ROW_B + kcB*16, pb + b_lo);
        asm volatile("cp.async.commit_group;");
    };

    const int q = lane >> 3, r = lane & 7;
    const uint32_t a_rel = (uint32_t)(wy*64 + (q & 1)*8 + r) * ROW_B + (q >> 1) * 16;
    const uint32_t b_rel = (uint32_t)(wx*32 + (q >> 1)*8 + r) * ROW_B + (q & 1) * 16;

    float acc[4][4][4];
    #pragma unroll
    for (int i = 0; i < 4; i++)
        #pragma unroll
        for (int j = 0; j < 4; j++)
            #pragma unroll
            for (int v = 0; v < 4; v++) acc[i][j][v] = 0.f;

    const int KT = K >> 5;
    issue(0, 0);

    for (int kt = 0; kt < KT; kt++) {
        const int nk = kt + 1;
        if (nk < KT) issue(nk & 1, nk);
        else asm volatile("cp.async.commit_group;");
        asm volatile("cp.async.wait_group 1;" ::: "memory");
        __syncthreads();

        const uint32_t st = sbase + (uint32_t)(kt & 1) * STAGE256;
        #pragma unroll
        for (int ks = 0; ks < 2; ks++) {
            uint32_t Bh[2][4], Bl[2][4];
            #pragma unroll
            for (int pr = 0; pr < 2; pr++) {
                uint32_t bd = st + 2*A256_B + b_rel + (uint32_t)pr*16*ROW_B + ks*32;
                ldsm4(bd,          Bh[pr]);
                ldsm4(bd + B256_B, Bl[pr]);
            }
            #pragma unroll
            for (int mt = 0; mt < 4; mt++) {
                uint32_t Ah[4], Al[4];
                uint32_t ad = st + a_rel + (uint32_t)mt*16*ROW_B + ks*32;
                ldsm4(ad,          Ah);
                ldsm4(ad + A256_B, Al);
                #pragma unroll
                for (int nt = 0; nt < 4; nt++) {
                    const uint32_t* bh = &Bh[nt >> 1][(nt & 1) * 2];
                    const uint32_t* bl = &Bl[nt >> 1][(nt & 1) * 2];
                    mma16816(acc[mt][nt], Ah, bh);
                    mma16816(acc[mt][nt], Ah, bl);
                    mma16816(acc[mt][nt], Al, bh);
                }
            }
        }
        __syncthreads();
    }

    const int gr = lane >> 2, gc = lane & 3;
    #pragma unroll
    for (int mt = 0; mt < 4; mt++)
        #pragma unroll
        for (int nt = 0; nt < 4; nt++)
            epilogue_store(ACT, OUTMODE, Cout, c_lo, N,
                           m0 + wy*64 + mt*16 + gr, n0 + wx*32 + nt*8 + 2*gc,
                           acc[mt][nt][0], acc[mt][nt][1],
                           acc[mt][nt][2], acc[mt][nt][3]);
}

// ============================================================================
// 3xBF16 NT GEMM, BM=BN=128 (R9 version, 2 CTAs/SM) — used for GEMM8 (N=768).
// ============================================================================
#define OP_B      (128*ROW_B)           // 10240
#define STAGE_B   (4*OP_B)              // 40960
#define TCSMEM    (2*STAGE_B)           // 81920

template<int ACT, int OUTMODE>
__global__ __launch_bounds__(256, 2) void tc_gemm(
    const __nv_bfloat16* __restrict__ A, size_t a_lo,
    const __nv_bfloat16* __restrict__ B, size_t b_lo,
    void* __restrict__ Cout, size_t c_lo,
    int N, int K)
{
    extern __shared__ char smem[];
    const uint32_t sbase = smem_u32(smem);
    const int tid  = threadIdx.x;
    const int wid  = tid >> 5;
    const int lane = tid & 31;
    const int m0 = blockIdx.y * 128;
    const int n0 = blockIdx.x * 128;
    const int wy = wid & 1;
    const int wx = wid >> 1;

    const int row0 = tid >> 2,          kc0 = tid & 3;
    const int row1 = (tid + 256) >> 2,  kc1 = (tid + 256) & 3;

    auto issue = [&](int s, int kt) {
        const uint32_t st = sbase + (uint32_t)s * STAGE_B;
        const size_t ka = (size_t)kt * 32;
        {
            const __nv_bfloat16* p = A + (size_t)(m0 + row0) * K + ka + kc0 * 8;
            cp16(st +        row0*ROW_B + kc0*16, p);
            cp16(st + OP_B + row0*ROW_B + kc0*16, p + a_lo);
            p = A + (size_t)(m0 + row1) * K + ka + kc1 * 8;
            cp16(st +        row1*ROW_B + kc1*16, p);
            cp16(st + OP_B + row1*ROW_B + kc1*16, p + a_lo);
        }
        {
            const __nv_bfloat16* p = B + (size_t)(n0 + row0) * K + ka + kc0 * 8;
            cp16(st + 2*OP_B + row0*ROW_B + kc0*16, p);
            cp16(st + 3*OP_B + row0*ROW_B + kc0*16, p + b_lo);
            p = B + (size_t)(n0 + row1) * K + ka + kc1 * 8;
            cp16(st + 2*OP_B + row1*ROW_B + kc1*16, p);
            cp16(st + 3*OP_B + row1*ROW_B + kc1*16, p + b_lo);
        }
        asm volatile("cp.async.commit_group;");
    };

    const int q = lane >> 3, r = lane & 7;
    const uint32_t a_rel = (uint32_t)(wy*64 + (q & 1)*8 + r) * ROW_B + (q >> 1) * 16;
    const uint32_t b_rel = (uint32_t)(wx*32 + (q >> 1)*8 + r) * ROW_B + (q & 1) * 16;

    float acc[4][4][4];
    #pragma unroll
    for (int i = 0; i < 4; i++)
        #pragma unroll
        for (int j = 0; j < 4; j++)
            #pragma unroll
            for (int v = 0; v < 4; v++) acc[i][j][v] = 0.f;

    const int KT = K >> 5;
    issue(0, 0);

    for (int kt = 0; kt < KT; kt++) {
        const int nk = kt + 1;
        if (nk < KT) issue(nk & 1, nk);
        else asm volatile("cp.async.commit_group;");
        asm volatile("cp.async.wait_group 1;" ::: "memory");
        __syncthreads();

        const uint32_t st = sbase + (uint32_t)(kt & 1) * STAGE_B;
        #pragma unroll
        for (int ks = 0; ks < 2; ks++) {
            uint32_t Bh[2][4], Bl[2][4];
            #pragma unroll
            for (int pr = 0; pr < 2; pr++) {
                uint32_t bd = st + 2*OP_B + b_rel + (uint32_t)pr*16*ROW_B + ks*32;
                ldsm4(bd,        Bh[pr]);
                ldsm4(bd + OP_B, Bl[pr]);
            }
            #pragma unroll
            for (int mt = 0; mt < 4; mt++) {
                uint32_t Ah[4], Al[4];
                uint32_t ad = st + a_rel + (uint32_t)mt*16*ROW_B + ks*32;
                ldsm4(ad,        Ah);
                ldsm4(ad + OP_B, Al);
                #pragma unroll
                for (int nt = 0; nt < 4; nt++) {
                    const uint32_t* bh = &Bh[nt >> 1][(nt & 1) * 2];
                    const uint32_t* bl = &Bl[nt >> 1][(nt & 1) * 2];
                    mma16816(acc[mt][nt], Ah, bh);
                    mma16816(acc[mt][nt], Ah, bl);
                    mma16816(acc[mt][nt], Al, bh);
                }
            }
        }
        __syncthreads();
    }

    const int gr = lane >> 2, gc = lane & 3;
    #pragma unroll
    for (int mt = 0; mt < 4; mt++)
        #pragma unroll
        for (int nt = 0; nt < 4; nt++)
            epilogue_store(ACT, OUTMODE, Cout, c_lo, N,
                           m0 + wy*64 + mt*16 + gr, n0 + wx*32 + nt*8 + 2*gc,
                           acc[mt][nt][0], acc[mt][nt][1],
                           acc[mt][nt][2], acc[mt][nt][3]);
}

// ----------------------------------------------------------------------------
// fp32 NT SGEMM for the dt projection (K=48). MODE 2 = softplus(x + bias[n]).
// ----------------------------------------------------------------------------
template<int MODE>
__global__ __launch_bounds__(256) void gemm_nt(
    const float* __restrict__ A, int lda,
    const float* __restrict__ B, int ldb,
    float* __restrict__ C, int ldc,
    int M, int N, int K,
    const float* __restrict__ bias)
{
    __shared__ float As[16][128];
    __shared__ float Bs[16][128];
    const int tid = threadIdx.x;
    const int m0 = blockIdx.y * 128;
    const int n0 = blockIdx.x * 128;
    const int tx = tid & 15;
    const int ty = tid >> 4;
    const int lr = tid >> 2;
    const int lq = tid & 3;

    float acc[8][8];
    #pragma unroll
    for (int i = 0; i < 8; i++)
        #pragma unroll
        for (int j = 0; j < 8; j++) acc[i][j] = 0.f;

    for (int k0 = 0; k0 < K; k0 += 16) {
        #pragma unroll
        for (int h = 0; h < 2; h++) {
            int m = m0 + h*64 + lr;
            float4 v = make_float4(0.f,0.f,0.f,0.f);
            if (m < M) v = *(const float4*)(A + (size_t)m*lda + k0 + lq*4);
            As[lq*4+0][h*64+lr] = v.x; As[lq*4+1][h*64+lr] = v.y;
            As[lq*4+2][h*64+lr] = v.z; As[lq*4+3][h*64+lr] = v.w;
        }
        #pragma unroll
        for (int h = 0; h < 2; h++) {
            int n = n0 + h*64 + lr;
            float4 v = make_float4(0.f,0.f,0.f,0.f);
            if (n < N) v = *(const float4*)(B + (size_t)n*ldb + k0 + lq*4);
            Bs[lq*4+0][h*64+lr] = v.x; Bs[lq*4+1][h*64+lr] = v.y;
            Bs[lq*4+2][h*64+lr] = v.z; Bs[lq*4+3][h*64+lr] = v.w;
        }
        __syncthreads();
        #pragma unroll
        for (int kk = 0; kk < 16; kk++) {
            float a[8], b[8];
            #pragma unroll
            for (int i = 0; i < 4; i++) {
                a[i]   = As[kk][ty*4 + i];
                a[4+i] = As[kk][64 + ty*4 + i];
                b[i]   = Bs[kk][tx*4 + i];
                b[4+i] = Bs[kk][64 + tx*4 + i];
            }
            #pragma unroll
            for (int i = 0; i < 8; i++)
                #pragma unroll
                for (int j = 0; j < 8; j++)
                    acc[i][j] = fmaf(a[i], b[j], acc[i][j]);
        }
        __syncthreads();
    }

    #pragma unroll
    for (int i = 0; i < 8; i++) {
        int m = m0 + ((i < 4) ? (ty*4 + i) : (64 + ty*4 + i - 4));
        if (m >= M) continue;
        #pragma unroll
        for (int j = 0; j < 8; j++) {
            int n = n0 + ((j < 4) ? (tx*4 + j) : (64 + tx*4 + j - 4));
            if (n >= N) continue;
            float v = acc[i][j];
            if (MODE == 2) {
                v += bias[n];
                v = (v > 20.f) ? v : log1pf(expf(v));
            }
            C[(size_t)m*ldc + n] = v;
        }
    }
}

// ----------------------------------------------------------------------------
// Small-N GEMM for x_proj: C[2048,80] = A[2048,1536] * W[80,1536]^T.
// ----------------------------------------------------------------------------
__global__ __launch_bounds__(256) void gemm_xproj(
    const float* __restrict__ A,
    const float* __restrict__ W,
    float* __restrict__ C)
{
    __shared__ float As[16][17];
    __shared__ float Bs[16][81];
    const int tid = threadIdx.x;
    const int m0 = blockIdx.x * 16;
    const int ty = tid >> 4;
    const int tx = tid & 15;

    float acc[5] = {0.f, 0.f, 0.f, 0.f, 0.f};
    for (int k0 = 0; k0 < DIq; k0 += 16) {
        {
            int row = tid >> 4, k = tid & 15;
            As[k][row] = A[(size_t)(m0 + row) * DIq + k0 + k];
        }
        #pragma unroll
        for (int j = 0; j < 5; j++) {
            int idx = tid + j * 256;
            if (idx < 80 * 16) {
                int n = idx >> 4, k = idx & 15;
                Bs[k][n] = W[(size_t)n * DIq + k0 + k];
            }
        }
        __syncthreads();
        #pragma unroll
        for (int kk = 0; kk < 16; kk++) {
            float a = As[kk][ty];
            #pragma unroll
            for (int j = 0; j < 5; j++)
                acc[j] = fmaf(a, Bs[kk][tx * 5 + j], acc[j]);
        }
        __syncthreads();
    }
    #pragma unroll
    for (int j = 0; j < 5; j++)
        C[(size_t)(m0 + ty) * SSMW + tx * 5 + j] = acc[j];
}

// ----------------------------------------------------------------------------
// Depthwise causal conv1d (K=4) + bias + SiLU.
// ----------------------------------------------------------------------------
__global__ void conv_silu_kernel(
    const float* __restrict__ proj,
    const float* __restrict__ conv_w,
    const float* __restrict__ conv_b,
    float* __restrict__ out)
{
    int idx = blockIdx.x * blockDim.x + threadIdx.x;
    if (idx >= TB * DIq) return;
    int d = idx % DIq;
    int t = idx / DIq;
    int l = t % Lq;
    float acc = conv_b[d];
    #pragma unroll
    for (int k = 0; k < Kq; k++) {
        int ls = l - (Kq - 1) + k;
        if (ls >= 0)
            acc = fmaf(conv_w[d*Kq + k], proj[(size_t)(t - (Kq-1) + k)*H2 + d], acc);
    }
    out[idx] = silu_f(acc);
}

// ----------------------------------------------------------------------------
// SSM scan, register-tiled in batches of 16 timesteps, double buffered.
// Lane j of each half-warp caches dt/hs/gate for timestep tb+j (broadcast by
// shfl), and every lane holds B/C columns for its own n across the batch.
// Arithmetic per step is identical to the R9 version.
// ----------------------------------------------------------------------------
__global__ __launch_bounds__(256) void scan_kernel(
    const float* __restrict__ dt,
    const float* __restrict__ hs,
    const float* __restrict__ ssmp,
    const float* __restrict__ proj,
    const float* __restrict__ A_log,
    const float* __restrict__ Dv,
    __nv_bfloat16* __restrict__ yh)
{
    int warp = (blockIdx.x * blockDim.x + threadIdx.x) >> 5;
    int lane = threadIdx.x & 31;
    if (warp >= Bq * (DIq/2)) return;
    int b  = warp / (DIq/2);
    int dp = warp % (DIq/2);
    int d  = dp*2 + (lane >> 4);
    int n  = lane & 15;

    const size_t ylo = (size_t)TB * DIq;
    float a  = -expf(A_log[d*Nq + n]);
    float Dd = Dv[d];
    float s  = 0.f;
    const int tbase = b * Lq;

    float BrA[16], CrA[16], dtA, hsA, gvA;
    float BrB[16], CrB[16], dtB, hsB, gvB;

    auto load_batch = [&](int bb, float* Br, float* Cr,
                          float& dtr, float& hsr, float& gvr) {
        const int tb = tbase + bb * 16;
        #pragma unroll
        for (int t = 0; t < 16; t++) {
            Br[t] = ssmp[(tb + t)*SSMW + Rq + n];
            Cr[t] = ssmp[(tb + t)*SSMW + Rq + Nq + n];
        }
        dtr = dt[(size_t)(tb + n)*DIq + d];
        hsr = hs[(size_t)(tb + n)*DIq + d];
        gvr = proj[(size_t)(tb + n)*H2 + DIq + d];
    };

    auto compute_batch = [&](int bb, const float* Br, const float* Cr,
                             float dtr, float hsr, float gvr) {
        const int tb = tbase + bb * 16;
        #pragma unroll
        for (int j = 0; j < 16; j++) {
            float dtv = __shfl_sync(0xffffffffu, dtr, j, 16);
            float hsv = __shfl_sync(0xffffffffu, hsr, j, 16);
            float gv  = __shfl_sync(0xffffffffu, gvr, j, 16);
            float dA  = __expf(dtv * a);
            s = fmaf(dA, s, dtv * Br[j] * hsv);
            float p = s * Cr[j];
            p += __shfl_xor_sync(0xffffffffu, p, 8, 16);
            p += __shfl_xor_sync(0xffffffffu, p, 4, 16);
            p += __shfl_xor_sync(0xffffffffu, p, 2, 16);
            p += __shfl_xor_sync(0xffffffffu, p, 1, 16);
            if (n == 0) {
                float v = (p + hsv * Dd) * silu_f(gv);
                __nv_bfloat16 h = __float2bfloat16(v);
                size_t idx = (size_t)(tb + j)*DIq + d;
                yh[idx]       = h;
                yh[ylo + idx] = __float2bfloat16(v - __bfloat162float(h));
            }
        }
    };

    const int NB = Lq / 16;   // 64 batches (even)
    load_batch(0, BrA, CrA, dtA, hsA, gvA);
    for (int bb = 0; bb < NB; bb += 2) {
        load_batch(bb + 1, BrB, CrB, dtB, hsB, gvB);
        compute_batch(bb, BrA, CrA, dtA, hsA, gvA);
        if (bb + 2 < NB) load_batch(bb + 2, BrA, CrA, dtA, hsA, gvA);
        compute_batch(bb + 1, BrB, CrB, dtB, hsB, gvB);
    }
}

// ----------------------------------------------------------------------------
extern "C" void kernel_launch(void* const* d_in, const int* in_sizes, int n_in,
                              void* d_out, int out_size)
{
    const float* x        = (const float*)d_in[0];
    const float* in_up_w  = (const float*)d_in[1];
    const float* in_dn_w  = (const float*)d_in[2];
    const float* conv_w   = (const float*)d_in[3];
    const float* conv_b   = (const float*)d_in[4];
    const float* xproj_w  = (const float*)d_in[5];
    const float* dt_w     = (const float*)d_in[6];
    const float* dt_b     = (const float*)d_in[7];
    const float* A_log    = (const float*)d_in[8];
    const float* Dv       = (const float*)d_in[9];
    const float* out_up_w = (const float*)d_in[10];
    const float* out_dn_w = (const float*)d_in[11];
    float* out            = (float*)d_out;

    float* proj;   cudaGetSymbolAddress((void**)&proj,   g_proj);
    float* hsconv; cudaGetSymbolAddress((void**)&hsconv, g_hsconv);
    float* ssmp;   cudaGetSymbolAddress((void**)&ssmp,   g_ssmp);
    float* dt;     cudaGetSymbolAddress((void**)&dt,     g_dt);
    __nv_bfloat16 *xbf, *h1bf, *ybf, *o1bf, *w1bf, *w2bf, *w3bf, *w4bf;
    cudaGetSymbolAddress((void**)&xbf,  g_x_bf);
    cudaGetSymbolAddress((void**)&h1bf, g_h1_bf);
    cudaGetSymbolAddress((void**)&ybf,  g_y_bf);
    cudaGetSymbolAddress((void**)&o1bf, g_o1_bf);
    cudaGetSymbolAddress((void**)&w1bf, g_w1_bf);
    cudaGetSymbolAddress((void**)&w2bf, g_w2_bf);
    cudaGetSymbolAddress((void**)&w3bf, g_w3_bf);
    cudaGetSymbolAddress((void**)&w4bf, g_w4_bf);

    cudaFuncSetAttribute(tc_gemm256<1,1>, cudaFuncAttributeMaxDynamicSharedMemorySize, TCSMEM256);
    cudaFuncSetAttribute(tc_gemm256<0,0>, cudaFuncAttributeMaxDynamicSharedMemorySize, TCSMEM256);
    cudaFuncSetAttribute(tc_gemm<0,0>,    cudaFuncAttributeMaxDynamicSharedMemorySize, TCSMEM);

    dim3 blk(256);
    const int SG = 1184;

    // 0) split inputs/weights to bf16 hi/lo
    split_kernel<<<SG, blk>>>((const float4*)x,        (uint2*)xbf,  (size_t)TB*Hq/4);
    split_kernel<<<SG, blk>>>((const float4*)in_up_w,  (uint2*)w1bf, (size_t)H1*Hq/4);
    split_kernel<<<SG, blk>>>((const float4*)in_dn_w,  (uint2*)w2bf, (size_t)H2*H1/4);
    split_kernel<<<SG, blk>>>((const float4*)out_up_w, (uint2*)w3bf, (size_t)H3*DIq/4);
    split_kernel<<<SG, blk>>>((const float4*)out_dn_w, (uint2*)w4bf, (size_t)Hq*H3/4);

    // 1) h1 = silu(x @ in_up_w^T), split output   [2048, 12288]
    tc_gemm256<1,1><<<dim3(H1/128, TB/256), dim3(512), TCSMEM256>>>(
        xbf, (size_t)TB*Hq, w1bf, (size_t)H1*Hq, h1bf, (size_t)TB*H1, H1, Hq);
    // 2) proj = h1 @ in_down_w^T, fp32 out        [2048, 3072]
    tc_gemm256<0,0><<<dim3(H2/128, TB/256), dim3(512), TCSMEM256>>>(
        h1bf, (size_t)TB*H1, w2bf, (size_t)H2*H1, proj, 0, H2, H1);
    // 3) depthwise causal conv + SiLU
    conv_silu_kernel<<<(TB*DIq + 255)/256, blk>>>(proj, conv_w, conv_b, hsconv);
    // 4) ssm_p = hsconv @ x_proj_w^T              [2048, 80]
    gemm_xproj<<<TB/16, blk>>>(hsconv, xproj_w, ssmp);
    // 5) dt = softplus(ts @ dt_w^T + dt_b)        [2048, 1536]
    gemm_nt<2><<<dim3(DIq/128, TB/128), blk>>>(ssmp, SSMW, dt_w, Rq,
                                               dt, DIq, TB, DIq, Rq, dt_b);
    // 6) SSM scan + skip + gate -> y (split bf16)
    scan_kernel<<<(Bq*(DIq/2)*32 + 255)/256, blk>>>(dt, hsconv, ssmp, proj,
                                                    A_log, Dv, ybf);
    // 7) out1 = silu(y @ out_up_w^T), split out   [2048, 6144]
    tc_gemm256<1,1><<<dim3(H3/128, TB/256), dim3(512), TCSMEM256>>>(
        ybf, (size_t)TB*DIq, w3bf, (size_t)H3*DIq, o1bf, (size_t)TB*H3, H3, DIq);
    // 8) out = out1 @ out_down_w^T, fp32 out      [2048, 768]
    tc_gemm<0,0><<<dim3(Hq/128, TB/128), blk, TCSMEM>>>(
        o1bf, (size_t)TB*H3, w4bf, (size_t)Hq*H3, out, 0, Hq, H3);
}

// round 11
// speedup vs baseline: 1.2005x; 1.2005x over previous
#include <cuda_runtime.h>
#include <cuda_bf16.h>
#include <math.h>
#include <stdint.h>

// Problem dimensions (fixed)
#define Bq   2
#define Lq   1024
#define Hq   768
#define DIq  1536
#define Nq   16
#define Kq   4
#define Rq   48
#define TB   (Bq*Lq)          // 2048 tokens
#define H1   (2*DIq*4)        // 12288
#define H2   (2*DIq)          // 3072
#define H3   (4*DIq)          // 6144
#define SSMW (Rq + 2*Nq)      // 80

// -------- fp32 scratch --------
__device__ __align__(16) float g_proj  [(size_t)TB * H2];
__device__ __align__(16) float g_hsconv[(size_t)TB * DIq];
__device__ __align__(16) float g_ssmp  [(size_t)TB * SSMW];
__device__ __align__(16) float g_dt    [(size_t)TB * DIq];

// -------- bf16 split scratch: hi in [0, n), lo in [n, 2n) --------
__device__ __align__(16) __nv_bfloat16 g_x_bf [2*(size_t)TB*Hq];
__device__ __align__(16) __nv_bfloat16 g_h1_bf[2*(size_t)TB*H1];
__device__ __align__(16) __nv_bfloat16 g_y_bf [2*(size_t)TB*DIq];
__device__ __align__(16) __nv_bfloat16 g_o1_bf[2*(size_t)TB*H3];
__device__ __align__(16) __nv_bfloat16 g_w1_bf[2*(size_t)H1*Hq];
__device__ __align__(16) __nv_bfloat16 g_w2_bf[2*(size_t)H2*H1];
__device__ __align__(16) __nv_bfloat16 g_w3_bf[2*(size_t)H3*DIq];
__device__ __align__(16) __nv_bfloat16 g_w4_bf[2*(size_t)Hq*H3];

__device__ __forceinline__ float silu_f(float x) {
    return x * (1.0f / (1.0f + __expf(-x)));
}

// ============================================================================
// fp32 -> (bf16 hi, bf16 lo) splitter.  dst hi at [0,n), lo at [n,2n).
// ============================================================================
__global__ void split_kernel(const float4* __restrict__ src,
                             uint2* __restrict__ dhi, size_t n4)
{
    size_t i = (size_t)blockIdx.x * blockDim.x + threadIdx.x;
    size_t stride = (size_t)gridDim.x * blockDim.x;
    uint2* dlo = dhi + n4;
    for (; i < n4; i += stride) {
        float4 v = src[i];
        __nv_bfloat162 h01 = __floats2bfloat162_rn(v.x, v.y);
        __nv_bfloat162 h23 = __floats2bfloat162_rn(v.z, v.w);
        float lx = v.x - __bfloat162float(h01.x);
        float ly = v.y - __bfloat162float(h01.y);
        float lz = v.z - __bfloat162float(h23.x);
        float lw = v.w - __bfloat162float(h23.y);
        __nv_bfloat162 l01 = __floats2bfloat162_rn(lx, ly);
        __nv_bfloat162 l23 = __floats2bfloat162_rn(lz, lw);
        dhi[i] = make_uint2(*(const uint32_t*)&h01, *(const uint32_t*)&h23);
        dlo[i] = make_uint2(*(const uint32_t*)&l01, *(const uint32_t*)&l23);
    }
}

// ============================================================================
// Common PTX helpers
// ============================================================================
__device__ __forceinline__ uint32_t smem_u32(const void* p) {
    uint32_t a;
    asm("{ .reg .u64 t; cvta.to.shared.u64 t, %1; cvt.u32.u64 %0, t; }"
        : "=r"(a) : "l"(p));
    return a;
}
__device__ __forceinline__ void cp16(uint32_t saddr, const void* g) {
    asm volatile("cp.async.cg.shared.global [%0], [%1], 16;" :: "r"(saddr), "l"(g));
}
__device__ __forceinline__ void ldsm4(uint32_t addr, uint32_t* r) {
    asm volatile("ldmatrix.sync.aligned.m8n8.x4.shared.b16 {%0,%1,%2,%3}, [%4];"
        : "=r"(r[0]), "=r"(r[1]), "=r"(r[2]), "=r"(r[3]) : "r"(addr));
}
__device__ __forceinline__ void mma16816(float* d, const uint32_t* a, const uint32_t* b) {
    asm volatile("mma.sync.aligned.m16n8k16.row.col.f32.bf16.bf16.f32 "
        "{%0,%1,%2,%3}, {%4,%5,%6,%7}, {%8,%9}, {%0,%1,%2,%3};"
        : "+f"(d[0]), "+f"(d[1]), "+f"(d[2]), "+f"(d[3])
        : "r"(a[0]), "r"(a[1]), "r"(a[2]), "r"(a[3]), "r"(b[0]), "r"(b[1]));
}

// ============================================================================
// 3xBF16 NT GEMM via mma.sync: C = epi(A * B^T), fp32 acc.
// BM=BN=128, BK=32, 256 threads (8 warps, 2x4), 2 stages, 2 CTAs/SM.
// Inner loop software-pipelines A fragments across mt (prefetch mt+1's
// ldmatrix during mt's MMAs).
// ACT: 0 none, 1 SiLU.  OUTMODE: 0 fp32 C, 1 split-bf16 C (hi base, lo +c_lo).
// ============================================================================
#define ROW_B     80                    // padded row stride bytes (32 bf16 -> 80B)
#define OP_B      (128*ROW_B)           // 10240 per operand tile
#define STAGE_B   (4*OP_B)              // 40960
#define TCSMEM    (2*STAGE_B)           // 81920

template<int ACT, int OUTMODE>
__global__ __launch_bounds__(256, 2) void tc_gemm(
    const __nv_bfloat16* __restrict__ A, size_t a_lo,
    const __nv_bfloat16* __restrict__ B, size_t b_lo,
    void* __restrict__ Cout, size_t c_lo,
    int N, int K)
{
    extern __shared__ char smem[];
    const uint32_t sbase = smem_u32(smem);
    const int tid  = threadIdx.x;
    const int wid  = tid >> 5;
    const int lane = tid & 31;
    const int m0 = blockIdx.y * 128;
    const int n0 = blockIdx.x * 128;
    const int wy = wid & 1;         // m half (0..1)
    const int wx = wid >> 1;        // n quarter (0..3)

    const int row0 = tid >> 2,          kc0 = tid & 3;
    const int row1 = (tid + 256) >> 2,  kc1 = (tid + 256) & 3;

    auto issue = [&](int s, int kt) {
        const uint32_t st = sbase + (uint32_t)s * STAGE_B;
        const size_t ka = (size_t)kt * 32;
        {
            const __nv_bfloat16* p = A + (size_t)(m0 + row0) * K + ka + kc0 * 8;
            cp16(st +        row0*ROW_B + kc0*16, p);
            cp16(st + OP_B + row0*ROW_B + kc0*16, p + a_lo);
            p = A + (size_t)(m0 + row1) * K + ka + kc1 * 8;
            cp16(st +        row1*ROW_B + kc1*16, p);
            cp16(st + OP_B + row1*ROW_B + kc1*16, p + a_lo);
        }
        {
            const __nv_bfloat16* p = B + (size_t)(n0 + row0) * K + ka + kc0 * 8;
            cp16(st + 2*OP_B + row0*ROW_B + kc0*16, p);
            cp16(st + 3*OP_B + row0*ROW_B + kc0*16, p + b_lo);
            p = B + (size_t)(n0 + row1) * K + ka + kc1 * 8;
            cp16(st + 2*OP_B + row1*ROW_B + kc1*16, p);
            cp16(st + 3*OP_B + row1*ROW_B + kc1*16, p + b_lo);
        }
        asm volatile("cp.async.commit_group;");
    };

    const int q = lane >> 3, r = lane & 7;
    const uint32_t a_rel = (uint32_t)(wy*64 + (q & 1)*8 + r) * ROW_B + (q >> 1) * 16;
    const uint32_t b_rel = (uint32_t)(wx*32 + (q >> 1)*8 + r) * ROW_B + (q & 1) * 16;

    float acc[4][4][4];
    #pragma unroll
    for (int i = 0; i < 4; i++)
        #pragma unroll
        for (int j = 0; j < 4; j++)
            #pragma unroll
            for (int v = 0; v < 4; v++) acc[i][j][v] = 0.f;

    const int KT = K >> 5;
    issue(0, 0);

    for (int kt = 0; kt < KT; kt++) {
        const int nk = kt + 1;
        if (nk < KT) issue(nk & 1, nk);
        else asm volatile("cp.async.commit_group;");
        asm volatile("cp.async.wait_group 1;" ::: "memory");
        __syncthreads();

        const uint32_t st = sbase + (uint32_t)(kt & 1) * STAGE_B;
        #pragma unroll
        for (int ks = 0; ks < 2; ks++) {
            uint32_t Bh[2][4], Bl[2][4];
            #pragma unroll
            for (int pr = 0; pr < 2; pr++) {
                uint32_t bd = st + 2*OP_B + b_rel + (uint32_t)pr*16*ROW_B + ks*32;
                ldsm4(bd,        Bh[pr]);
                ldsm4(bd + OP_B, Bl[pr]);
            }
            // A-fragment double buffer: prefetch mt+1 during mt's MMAs
            uint32_t Af[2][2][4];     // [buf][limb][4]
            {
                uint32_t ad = st + a_rel + ks*32;
                ldsm4(ad,        Af[0][0]);
                ldsm4(ad + OP_B, Af[0][1]);
            }
            #pragma unroll
            for (int mt = 0; mt < 4; mt++) {
                if (mt < 3) {
                    uint32_t ad = st + a_rel + (uint32_t)(mt+1)*16*ROW_B + ks*32;
                    ldsm4(ad,        Af[(mt+1) & 1][0]);
                    ldsm4(ad + OP_B, Af[(mt+1) & 1][1]);
                }
                const uint32_t* Ah = Af[mt & 1][0];
                const uint32_t* Al = Af[mt & 1][1];
                #pragma unroll
                for (int nt = 0; nt < 4; nt++) {
                    const uint32_t* bh = &Bh[nt >> 1][(nt & 1) * 2];
                    const uint32_t* bl = &Bl[nt >> 1][(nt & 1) * 2];
                    mma16816(acc[mt][nt], Ah, bh);
                    mma16816(acc[mt][nt], Ah, bl);
                    mma16816(acc[mt][nt], Al, bh);
                }
            }
        }
        __syncthreads();
    }

    // ---- epilogue ----
    const int gr = lane >> 2, gc = lane & 3;
    #pragma unroll
    for (int mt = 0; mt < 4; mt++) {
        #pragma unroll
        for (int nt = 0; nt < 4; nt++) {
            const int row = m0 + wy*64 + mt*16 + gr;
            const int col = n0 + wx*32 + nt*8 + 2*gc;
            float f0 = acc[mt][nt][0], f1 = acc[mt][nt][1];
            float f2 = acc[mt][nt][2], f3 = acc[mt][nt][3];
            if (ACT == 1) { f0 = silu_f(f0); f1 = silu_f(f1); f2 = silu_f(f2); f3 = silu_f(f3); }
            if (OUTMODE == 0) {
                float* C = (float*)Cout;
                *(float2*)(C + (size_t)row * N + col)       = make_float2(f0, f1);
                *(float2*)(C + (size_t)(row + 8) * N + col) = make_float2(f2, f3);
            } else {
                __nv_bfloat16* Ch = (__nv_bfloat16*)Cout;
                __nv_bfloat162 h01 = __floats2bfloat162_rn(f0, f1);
                __nv_bfloat162 l01 = __floats2bfloat162_rn(f0 - __bfloat162float(h01.x),
                                                           f1 - __bfloat162float(h01.y));
                __nv_bfloat162 h23 = __floats2bfloat162_rn(f2, f3);
                __nv_bfloat162 l23 = __floats2bfloat162_rn(f2 - __bfloat162float(h23.x),
                                                           f3 - __bfloat162float(h23.y));
                *(__nv_bfloat162*)(Ch + (size_t)row * N + col)              = h01;
                *(__nv_bfloat162*)(Ch + c_lo + (size_t)row * N + col)       = l01;
                *(__nv_bfloat162*)(Ch + (size_t)(row + 8) * N + col)        = h23;
                *(__nv_bfloat162*)(Ch + c_lo + (size_t)(row + 8) * N + col) = l23;
            }
        }
    }
}

// ----------------------------------------------------------------------------
// fp32 NT SGEMM for the dt projection (K=48). MODE 2 = softplus(x + bias[n]).
// ----------------------------------------------------------------------------
template<int MODE>
__global__ __launch_bounds__(256) void gemm_nt(
    const float* __restrict__ A, int lda,
    const float* __restrict__ B, int ldb,
    float* __restrict__ C, int ldc,
    int M, int N, int K,
    const float* __restrict__ bias)
{
    __shared__ float As[16][128];
    __shared__ float Bs[16][128];
    const int tid = threadIdx.x;
    const int m0 = blockIdx.y * 128;
    const int n0 = blockIdx.x * 128;
    const int tx = tid & 15;
    const int ty = tid >> 4;
    const int lr = tid >> 2;
    const int lq = tid & 3;

    float acc[8][8];
    #pragma unroll
    for (int i = 0; i < 8; i++)
        #pragma unroll
        for (int j = 0; j < 8; j++) acc[i][j] = 0.f;

    for (int k0 = 0; k0 < K; k0 += 16) {
        #pragma unroll
        for (int h = 0; h < 2; h++) {
            int m = m0 + h*64 + lr;
            float4 v = make_float4(0.f,0.f,0.f,0.f);
            if (m < M) v = *(const float4*)(A + (size_t)m*lda + k0 + lq*4);
            As[lq*4+0][h*64+lr] = v.x; As[lq*4+1][h*64+lr] = v.y;
            As[lq*4+2][h*64+lr] = v.z; As[lq*4+3][h*64+lr] = v.w;
        }
        #pragma unroll
        for (int h = 0; h < 2; h++) {
            int n = n0 + h*64 + lr;
            float4 v = make_float4(0.f,0.f,0.f,0.f);
            if (n < N) v = *(const float4*)(B + (size_t)n*ldb + k0 + lq*4);
            Bs[lq*4+0][h*64+lr] = v.x; Bs[lq*4+1][h*64+lr] = v.y;
            Bs[lq*4+2][h*64+lr] = v.z; Bs[lq*4+3][h*64+lr] = v.w;
        }
        __syncthreads();
        #pragma unroll
        for (int kk = 0; kk < 16; kk++) {
            float a[8], b[8];
            #pragma unroll
            for (int i = 0; i < 4; i++) {
                a[i]   = As[kk][ty*4 + i];
                a[4+i] = As[kk][64 + ty*4 + i];
                b[i]   = Bs[kk][tx*4 + i];
                b[4+i] = Bs[kk][64 + tx*4 + i];
            }
            #pragma unroll
            for (int i = 0; i < 8; i++)
                #pragma unroll
                for (int j = 0; j < 8; j++)
                    acc[i][j] = fmaf(a[i], b[j], acc[i][j]);
        }
        __syncthreads();
    }

    #pragma unroll
    for (int i = 0; i < 8; i++) {
        int m = m0 + ((i < 4) ? (ty*4 + i) : (64 + ty*4 + i - 4));
        if (m >= M) continue;
        #pragma unroll
        for (int j = 0; j < 8; j++) {
            int n = n0 + ((j < 4) ? (tx*4 + j) : (64 + tx*4 + j - 4));
            if (n >= N) continue;
            float v = acc[i][j];
            if (MODE == 2) {
                v += bias[n];
                v = (v > 20.f) ? v : log1pf(expf(v));
            }
            C[(size_t)m*ldc + n] = v;
        }
    }
}

// ----------------------------------------------------------------------------
// Small-N GEMM for x_proj: C[2048,80] = A[2048,1536] * W[80,1536]^T.
// ----------------------------------------------------------------------------
__global__ __launch_bounds__(256) void gemm_xproj(
    const float* __restrict__ A,
    const float* __restrict__ W,
    float* __restrict__ C)
{
    __shared__ float As[16][17];
    __shared__ float Bs[16][81];
    const int tid = threadIdx.x;
    const int m0 = blockIdx.x * 16;
    const int ty = tid >> 4;
    const int tx = tid & 15;

    float acc[5] = {0.f, 0.f, 0.f, 0.f, 0.f};
    for (int k0 = 0; k0 < DIq; k0 += 16) {
        {
            int row = tid >> 4, k = tid & 15;
            As[k][row] = A[(size_t)(m0 + row) * DIq + k0 + k];
        }
        #pragma unroll
        for (int j = 0; j < 5; j++) {
            int idx = tid + j * 256;
            if (idx < 80 * 16) {
                int n = idx >> 4, k = idx & 15;
                Bs[k][n] = W[(size_t)n * DIq + k0 + k];
            }
        }
        __syncthreads();
        #pragma unroll
        for (int kk = 0; kk < 16; kk++) {
            float a = As[kk][ty];
            #pragma unroll
            for (int j = 0; j < 5; j++)
                acc[j] = fmaf(a, Bs[kk][tx * 5 + j], acc[j]);
        }
        __syncthreads();
    }
    #pragma unroll
    for (int j = 0; j < 5; j++)
        C[(size_t)(m0 + ty) * SSMW + tx * 5 + j] = acc[j];
}

// ----------------------------------------------------------------------------
// Depthwise causal conv1d (K=4) + bias + SiLU.
// ----------------------------------------------------------------------------
__global__ void conv_silu_kernel(
    const float* __restrict__ proj,
    const float* __restrict__ conv_w,
    const float* __restrict__ conv_b,
    float* __restrict__ out)
{
    int idx = blockIdx.x * blockDim.x + threadIdx.x;
    if (idx >= TB * DIq) return;
    int d = idx % DIq;
    int t = idx / DIq;
    int l = t % Lq;
    float acc = conv_b[d];
    #pragma unroll
    for (int k = 0; k < Kq; k++) {
        int ls = l - (Kq - 1) + k;
        if (ls >= 0)
            acc = fmaf(conv_w[d*Kq + k], proj[(size_t)(t - (Kq-1) + k)*H2 + d], acc);
    }
    out[idx] = silu_f(acc);
}

// ----------------------------------------------------------------------------
// SSM scan with next-step prefetch (R9 version). Writes y as split bf16.
// ----------------------------------------------------------------------------
__global__ __launch_bounds__(256) void scan_kernel(
    const float* __restrict__ dt,
    const float* __restrict__ hs,
    const float* __restrict__ ssmp,
    const float* __restrict__ proj,
    const float* __restrict__ A_log,
    const float* __restrict__ Dv,
    __nv_bfloat16* __restrict__ yh)
{
    int warp = (blockIdx.x * blockDim.x + threadIdx.x) >> 5;
    int lane = threadIdx.x & 31;
    if (warp >= Bq * (DIq/2)) return;
    int b  = warp / (DIq/2);
    int dp = warp % (DIq/2);
    int d  = dp*2 + (lane >> 4);
    int n  = lane & 15;

    const size_t ylo = (size_t)TB * DIq;
    float a  = -expf(A_log[d*Nq + n]);
    float Dd = Dv[d];
    float s  = 0.f;
    const int tbase = b * Lq;

    float dtv = dt[(size_t)tbase*DIq + d];
    float hsv = hs[(size_t)tbase*DIq + d];
    float Bv  = ssmp[tbase*SSMW + Rq + n];
    float Cv  = ssmp[tbase*SSMW + Rq + Nq + n];
    float gv  = proj[(size_t)tbase*H2 + DIq + d];

    for (int l = 0; l < Lq; l++) {
        const int t = tbase + l;
        float dtv_n = 0.f, hsv_n = 0.f, Bv_n = 0.f, Cv_n = 0.f, gv_n = 0.f;
        if (l + 1 < Lq) {
            const int tn = t + 1;
            dtv_n = dt[(size_t)tn*DIq + d];
            hsv_n = hs[(size_t)tn*DIq + d];
            Bv_n  = ssmp[tn*SSMW + Rq + n];
            Cv_n  = ssmp[tn*SSMW + Rq + Nq + n];
            gv_n  = proj[(size_t)tn*H2 + DIq + d];
        }
        float dA = __expf(dtv * a);
        s = fmaf(dA, s, dtv * Bv * hsv);
        float p = s * Cv;
        p += __shfl_xor_sync(0xffffffffu, p, 8, 16);
        p += __shfl_xor_sync(0xffffffffu, p, 4, 16);
        p += __shfl_xor_sync(0xffffffffu, p, 2, 16);
        p += __shfl_xor_sync(0xffffffffu, p, 1, 16);
        if (n == 0) {
            float v = (p + hsv * Dd) * silu_f(gv);
            __nv_bfloat16 h = __float2bfloat16(v);
            size_t idx = (size_t)t*DIq + d;
            yh[idx]       = h;
            yh[ylo + idx] = __float2bfloat16(v - __bfloat162float(h));
        }
        dtv = dtv_n; hsv = hsv_n; Bv = Bv_n; Cv = Cv_n; gv = gv_n;
    }
}

// ----------------------------------------------------------------------------
extern "C" void kernel_launch(void* const* d_in, const int* in_sizes, int n_in,
                              void* d_out, int out_size)
{
    const float* x        = (const float*)d_in[0];
    const float* in_up_w  = (const float*)d_in[1];
    const float* in_dn_w  = (const float*)d_in[2];
    const float* conv_w   = (const float*)d_in[3];
    const float* conv_b   = (const float*)d_in[4];
    const float* xproj_w  = (const float*)d_in[5];
    const float* dt_w     = (const float*)d_in[6];
    const float* dt_b     = (const float*)d_in[7];
    const float* A_log    = (const float*)d_in[8];
    const float* Dv       = (const float*)d_in[9];
    const float* out_up_w = (const float*)d_in[10];
    const float* out_dn_w = (const float*)d_in[11];
    float* out            = (float*)d_out;

    float* proj;   cudaGetSymbolAddress((void**)&proj,   g_proj);
    float* hsconv; cudaGetSymbolAddress((void**)&hsconv, g_hsconv);
    float* ssmp;   cudaGetSymbolAddress((void**)&ssmp,   g_ssmp);
    float* dt;     cudaGetSymbolAddress((void**)&dt,     g_dt);
    __nv_bfloat16 *xbf, *h1bf, *ybf, *o1bf, *w1bf, *w2bf, *w3bf, *w4bf;
    cudaGetSymbolAddress((void**)&xbf,  g_x_bf);
    cudaGetSymbolAddress((void**)&h1bf, g_h1_bf);
    cudaGetSymbolAddress((void**)&ybf,  g_y_bf);
    cudaGetSymbolAddress((void**)&o1bf, g_o1_bf);
    cudaGetSymbolAddress((void**)&w1bf, g_w1_bf);
    cudaGetSymbolAddress((void**)&w2bf, g_w2_bf);
    cudaGetSymbolAddress((void**)&w3bf, g_w3_bf);
    cudaGetSymbolAddress((void**)&w4bf, g_w4_bf);

    cudaFuncSetAttribute(tc_gemm<1,1>, cudaFuncAttributeMaxDynamicSharedMemorySize, TCSMEM);
    cudaFuncSetAttribute(tc_gemm<0,0>, cudaFuncAttributeMaxDynamicSharedMemorySize, TCSMEM);

    dim3 blk(256);
    const int SG = 1184;

    // 0) split inputs/weights to bf16 hi/lo
    split_kernel<<<SG, blk>>>((const float4*)x,        (uint2*)xbf,  (size_t)TB*Hq/4);
    split_kernel<<<SG, blk>>>((const float4*)in_up_w,  (uint2*)w1bf, (size_t)H1*Hq/4);
    split_kernel<<<SG, blk>>>((const float4*)in_dn_w,  (uint2*)w2bf, (size_t)H2*H1/4);
    split_kernel<<<SG, blk>>>((const float4*)out_up_w, (uint2*)w3bf, (size_t)H3*DIq/4);
    split_kernel<<<SG, blk>>>((const float4*)out_dn_w, (uint2*)w4bf, (size_t)Hq*H3/4);

    // 1) h1 = silu(x @ in_up_w^T), split output   [2048, 12288]
    tc_gemm<1,1><<<dim3(H1/128, TB/128), blk, TCSMEM>>>(
        xbf, (size_t)TB*Hq, w1bf, (size_t)H1*Hq, h1bf, (size_t)TB*H1, H1, Hq);
    // 2) proj = h1 @ in_down_w^T, fp32 out        [2048, 3072]
    tc_gemm<0,0><<<dim3(H2/128, TB/128), blk, TCSMEM>>>(
        h1bf, (size_t)TB*H1, w2bf, (size_t)H2*H1, proj, 0, H2, H1);
    // 3) depthwise causal conv + SiLU
    conv_silu_kernel<<<(TB*DIq + 255)/256, blk>>>(proj, conv_w, conv_b, hsconv);
    // 4) ssm_p = hsconv @ x_proj_w^T              [2048, 80]
    gemm_xproj<<<TB/16, blk>>>(hsconv, xproj_w, ssmp);
    // 5) dt = softplus(ts @ dt_w^T + dt_b)        [2048, 1536]
    gemm_nt<2><<<dim3(DIq/128, TB/128), blk>>>(ssmp, SSMW, dt_w, Rq,
                                               dt, DIq, TB, DIq, Rq, dt_b);
    // 6) SSM scan + skip + gate -> y (split bf16)
    scan_kernel<<<(Bq*(DIq/2)*32 + 255)/256, blk>>>(dt, hsconv, ssmp, proj,
                                                    A_log, Dv, ybf);
    // 7) out1 = silu(y @ out_up_w^T), split out   [2048, 6144]
    tc_gemm<1,1><<<dim3(H3/128, TB/128), blk, TCSMEM>>>(
        ybf, (size_t)TB*DIq, w3bf, (size_t)H3*DIq, o1bf, (size_t)TB*H3, H3, DIq);
    // 8) out = out1 @ out_down_w^T, fp32 out      [2048, 768]
    tc_gemm<0,0><<<dim3(Hq/128, TB/128), blk, TCSMEM>>>(
        o1bf, (size_t)TB*H3, w4bf, (size_t)Hq*H3, out, 0, Hq, H3);
}